// round 4
// baseline (speedup 1.0000x reference)
#include <cuda_runtime.h>
#include <math.h>

// Problem constants
#define BB   1024   // batch
#define TT   128    // seq len
#define CC   1024   // embed dim
#define HH   64     // head size
#define N3   192    // combined QKV output cols
#define KC   32     // K-chunk for projection GEMM

// smem layout (floats):
//   qkv: 3 * 128 * 65   (Q,K,V padded pitch 65 to kill bank conflicts)
//   S  : 128 * 128      (score matrix; its region is reused as GEMM staging
//                        buffers xs[128*32] + ws[32*192] during projection)
#define QKV_PITCH 65
#define QKV_FLOATS (3 * TT * QKV_PITCH)      // 24960
#define S_FLOATS   (TT * TT)                 // 16384
#define SMEM_FLOATS (QKV_FLOATS + S_FLOATS)  // 41344 -> 165376 bytes

__global__ __launch_bounds__(512, 1)
void head_attn_fused(const float* __restrict__ x,
                     const float* __restrict__ Wk,
                     const float* __restrict__ Wq,
                     const float* __restrict__ Wv,
                     float* __restrict__ out)
{
    extern __shared__ float sm[];
    float* qkv = sm;                    // [3][128][65]
    float* S   = sm + QKV_FLOATS;       // [128][128]
    float* xs  = S;                     // staging: [128][32]
    float* ws  = S + TT * KC;           // staging: [32][192]

    const int b   = blockIdx.x;
    const int tid = threadIdx.x;
    const float* xb = x + (size_t)b * TT * CC;

    // ---------------- Phase 1: QKV projection GEMM ----------------
    // Output [128 rows x 192 cols]. Thread grid 16(M) x 32(N), tile 8x6.
    const int tm = tid >> 5;   // 0..15 -> rows tm*8 .. tm*8+7
    const int tn = tid & 31;   // 0..31 -> cols tn*6 .. tn*6+5

    float acc[8][6];
#pragma unroll
    for (int i = 0; i < 8; ++i)
#pragma unroll
        for (int j = 0; j < 6; ++j) acc[i][j] = 0.f;

    for (int c0 = 0; c0 < CC; c0 += KC) {
        __syncthreads();  // previous chunk's compute done before overwrite

        // load x chunk [128][32] as float4 (1024 float4, 2/thread)
        for (int i = tid; i < TT * KC / 4; i += 512) {
            int row = i >> 3;
            int c4  = i & 7;
            float4 v = ((const float4*)(xb + (size_t)row * CC + c0))[c4];
            ((float4*)xs)[row * 8 + c4] = v;
        }
        // load combined weight chunk [32][192]: cols 0-63 Q, 64-127 K, 128-191 V
        for (int i = tid; i < KC * N3 / 4; i += 512) {
            int row = i / 48;          // 0..31
            int j4  = i % 48;          // 0..47
            const float* src = (j4 < 16) ? Wq : (j4 < 32) ? Wk : Wv;
            int jj = j4 & 15;
            float4 v = ((const float4*)(src + (size_t)(c0 + row) * HH))[jj];
            ((float4*)ws)[row * 48 + j4] = v;
        }
        __syncthreads();

#pragma unroll 4
        for (int kk = 0; kk < KC; ++kk) {
            float a[8], bv[6];
#pragma unroll
            for (int i = 0; i < 8; ++i) a[i] = xs[(tm * 8 + i) * KC + kk];
#pragma unroll
            for (int j = 0; j < 6; ++j) bv[j] = ws[kk * N3 + tn * 6 + j];
#pragma unroll
            for (int i = 0; i < 8; ++i)
#pragma unroll
                for (int j = 0; j < 6; ++j)
                    acc[i][j] = fmaf(a[i], bv[j], acc[i][j]);
        }
    }
    __syncthreads();

    // scatter accumulators into padded Q/K/V smem
#pragma unroll
    for (int i = 0; i < 8; ++i) {
#pragma unroll
        for (int j = 0; j < 6; ++j) {
            int r   = tm * 8 + i;
            int col = tn * 6 + j;
            int m   = col >> 6;        // 0=Q,1=K,2=V
            int h   = col & 63;
            qkv[m * TT * QKV_PITCH + r * QKV_PITCH + h] = acc[i][j];
        }
    }
    __syncthreads();

    float* qs = qkv;
    float* ks = qkv + TT * QKV_PITCH;
    float* vs = qkv + 2 * TT * QKV_PITCH;

    // ---------------- Phase 2: scores S = Q @ K^T (causal) ----------------
    {
        const int t  = tid >> 2;           // 0..127
        const int sb = (tid & 3) * 32;     // s block base
        const float* qrow = qs + t * QKV_PITCH;
        for (int so = 0; so < 32; ++so) {
            int s = sb + so;
            if (s <= t) {
                const float* krow = ks + s * QKV_PITCH;
                float sum = 0.f;
#pragma unroll 16
                for (int h = 0; h < HH; ++h)
                    sum = fmaf(qrow[h], krow[h], sum);
                S[t * TT + s] = sum;
            }
        }
    }
    __syncthreads();

    // ---------------- Phase 3: causal softmax per row ----------------
    {
        const int warp = tid >> 5;
        const int lane = tid & 31;
        for (int rr = 0; rr < 8; ++rr) {
            int t = warp * 8 + rr;
            float vals[4];
            float mx = -INFINITY;
#pragma unroll
            for (int j = 0; j < 4; ++j) {
                int s = lane + j * 32;
                vals[j] = (s <= t) ? S[t * TT + s] : -INFINITY;
                mx = fmaxf(mx, vals[j]);
            }
#pragma unroll
            for (int o = 16; o > 0; o >>= 1)
                mx = fmaxf(mx, __shfl_xor_sync(0xffffffffu, mx, o));
            float sum = 0.f;
#pragma unroll
            for (int j = 0; j < 4; ++j) {
                int s = lane + j * 32;
                vals[j] = (s <= t) ? __expf(vals[j] - mx) : 0.f;
                sum += vals[j];
            }
#pragma unroll
            for (int o = 16; o > 0; o >>= 1)
                sum += __shfl_xor_sync(0xffffffffu, sum, o);
            float inv = 1.f / sum;
#pragma unroll
            for (int j = 0; j < 4; ++j)
                S[t * TT + lane + j * 32] = vals[j] * inv;  // s>t -> exactly 0
        }
    }
    __syncthreads();

    // ---------------- Phase 4: out = S @ V ----------------
    {
        const int h  = tid & 63;
        const int tg = tid >> 6;   // 0..7
        float* ob = out + (size_t)b * TT * HH;
        for (int rr = 0; rr < 16; ++rr) {
            int t = rr * 8 + tg;
            const float* srow = S + t * TT;
            float sum = 0.f;
            for (int s = 0; s <= t; ++s)
                sum = fmaf(srow[s], vs[s * QKV_PITCH + h], sum);
            ob[t * HH + h] = sum;
        }
    }
}

extern "C" void kernel_launch(void* const* d_in, const int* in_sizes, int n_in,
                              void* d_out, int out_size)
{
    const float* x  = (const float*)d_in[0];
    const float* Wk = (const float*)d_in[1];
    const float* Wq = (const float*)d_in[2];
    const float* Wv = (const float*)d_in[3];
    float* out = (float*)d_out;

    const int smem_bytes = SMEM_FLOATS * (int)sizeof(float);
    static int smem_set = 0;
    if (!smem_set) {
        cudaFuncSetAttribute(head_attn_fused,
                             cudaFuncAttributeMaxDynamicSharedMemorySize,
                             smem_bytes);
        smem_set = 1;
    }
    head_attn_fused<<<BB, 512, smem_bytes>>>(x, Wk, Wq, Wv, out);
}

// round 8
// speedup vs baseline: 1.4415x; 1.4415x over previous
#include <cuda_runtime.h>
#include <math.h>
#include <stdint.h>

// ---------------- problem constants ----------------
#define BB   1024
#define TT   128
#define CC   1024
#define HH   64
#define N3   192            // Q|K|V combined output cols

#define KCH  32             // K-chunk (floats) staged per iteration
#define NCHUNKS (CC/KCH)    // 32
#define NK8  (CC/8)         // 128 k8 groups total
#define NTILES (N3/8)       // 24 n-tiles of 8

// ---------------- smem layout (floats) ----------------
// union:
//   phase1 staging: xs_hi[128][33] + xs_lo[128][33]  (8448 floats)
//   post-projection: qkv[3][128][65] + S[128][128]
#define QKV_PITCH  65
#define QKV_FLOATS (3*TT*QKV_PITCH)          // 24960
#define S_FLOATS   (TT*TT)                   // 16384
#define DATA_FLOATS (QKV_FLOATS + S_FLOATS)  // 41344
#define SMEM_BYTES (DATA_FLOATS*4)           // 165376

#define XS_PITCH 33

// B pre-packed in m16n8k8 tf32 fragment order:
// Bfrag[k8(128)][nt(24)][hl(2)][lane(32)] float2{b0,b1}
//   b0: k = k8*8 + (lane&3),  n = nt*8 + (lane>>2)
//   b1: k = k8*8 + (lane&3)+4, same n
__device__ __align__(16) float2 Bfrag_g[NK8 * NTILES * 2 * 32];

// ---------------- helpers ----------------
__device__ __forceinline__ float tf32_rnd(float x) {
    unsigned u;
    asm("cvt.rna.tf32.f32 %0, %1;" : "=r"(u) : "f"(x));
    return __uint_as_float(u);
}

__device__ __forceinline__ void mma_tf32(float* d, const unsigned* a, float2 b) {
    unsigned b0 = __float_as_uint(b.x);
    unsigned b1 = __float_as_uint(b.y);
    asm volatile(
        "mma.sync.aligned.m16n8k8.row.col.f32.tf32.tf32.f32 "
        "{%0,%1,%2,%3}, {%4,%5,%6,%7}, {%8,%9}, {%0,%1,%2,%3};"
        : "+f"(d[0]), "+f"(d[1]), "+f"(d[2]), "+f"(d[3])
        : "r"(a[0]), "r"(a[1]), "r"(a[2]), "r"(a[3]), "r"(b0), "r"(b1));
}

// ---------------- prep kernel: pack W into tf32 hi/lo fragments ----------------
__global__ void prep_w(const float* __restrict__ Wk,
                       const float* __restrict__ Wq,
                       const float* __restrict__ Wv)
{
    int i = blockIdx.x * blockDim.x + threadIdx.x;   // 0 .. 196607
    if (i >= NK8 * NTILES * 2 * 32) return;
    int lane  = i & 31;
    int rest  = i >> 5;
    int hl    = rest & 1;
    int rest2 = rest >> 1;          // k8*24 + nt
    int nt    = rest2 % NTILES;
    int k8    = rest2 / NTILES;     // 0..127
    int n     = nt * 8 + (lane >> 2);
    int mat   = n >> 6;             // 0=Q,1=K,2=V
    int h     = n & 63;
    const float* W = (mat == 0) ? Wq : (mat == 1) ? Wk : Wv;
    int k0 = k8 * 8 + (lane & 3);
    float w0 = W[k0 * HH + h];
    float w1 = W[(k0 + 4) * HH + h];
    float h0 = tf32_rnd(w0), h1 = tf32_rnd(w1);
    float2 v;
    if (hl == 0) { v.x = h0; v.y = h1; }
    else         { v.x = tf32_rnd(w0 - h0); v.y = tf32_rnd(w1 - h1); }
    Bfrag_g[i] = v;
}

// ---------------- main fused kernel ----------------
__global__ __launch_bounds__(512, 1)
void head_attn_mma(const float* __restrict__ x, float* __restrict__ out)
{
    extern __shared__ float data[];
    float* qkv   = data;                       // [3][128][65] (after projection)
    float* S     = data + QKV_FLOATS;          // [128][128]
    float* xs_hi = data;                       // [128][33] (phase-1 staging)
    float* xs_lo = data + TT * XS_PITCH;

    const int b    = blockIdx.x;
    const int tid  = threadIdx.x;
    const int warp = tid >> 5;
    const int lane = tid & 31;
    const int warpM = warp >> 1;    // 0..7  -> rows warpM*16 ..+15
    const int warpN = warp & 1;     // 0..1  -> n-tiles warpN*12 ..+11
    const float* xb = x + (size_t)b * TT * CC;

    // ---- Phase 1: QKV projection, tf32 mma.sync with 3-term split ----
    float acc[12][4];
#pragma unroll
    for (int nt = 0; nt < 12; ++nt)
#pragma unroll
        for (int j = 0; j < 4; ++j) acc[nt][j] = 0.f;

    // prefetch chunk 0 (2 float4 per thread)
    const int prow0 = tid >> 3,          pj40 = tid & 7;
    const int prow1 = (tid + 512) >> 3,  pj41 = (tid + 512) & 7;
    float4 pf0 = ((const float4*)(xb + (size_t)prow0 * CC))[pj40];
    float4 pf1 = ((const float4*)(xb + (size_t)prow1 * CC))[pj41];

    const int r0 = warpM * 16 + (lane >> 2);
    const int kk = lane & 3;

    for (int ch = 0; ch < NCHUNKS; ++ch) {
        __syncthreads();   // previous compute finished reading stage

        // convert + store this chunk's x into xs_hi/xs_lo
        {
            float v[4] = {pf0.x, pf0.y, pf0.z, pf0.w};
#pragma unroll
            for (int e = 0; e < 4; ++e) {
                float hi = tf32_rnd(v[e]);
                xs_hi[prow0 * XS_PITCH + pj40 * 4 + e] = hi;
                xs_lo[prow0 * XS_PITCH + pj40 * 4 + e] = tf32_rnd(v[e] - hi);
            }
            float w[4] = {pf1.x, pf1.y, pf1.z, pf1.w};
#pragma unroll
            for (int e = 0; e < 4; ++e) {
                float hi = tf32_rnd(w[e]);
                xs_hi[prow1 * XS_PITCH + pj41 * 4 + e] = hi;
                xs_lo[prow1 * XS_PITCH + pj41 * 4 + e] = tf32_rnd(w[e] - hi);
            }
        }
        // prefetch next chunk (overlaps the MMA compute below)
        if (ch + 1 < NCHUNKS) {
            int c0n = (ch + 1) * KCH;
            pf0 = ((const float4*)(xb + (size_t)prow0 * CC + c0n))[pj40];
            pf1 = ((const float4*)(xb + (size_t)prow1 * CC + c0n))[pj41];
        }
        __syncthreads();

        // compute: 4 k8-groups x 12 n-tiles x 3 mmas
#pragma unroll
        for (int k8l = 0; k8l < 4; ++k8l) {
            const int c0 = k8l * 8 + kk;
            unsigned ah[4], al[4];
            ah[0] = __float_as_uint(xs_hi[r0 * XS_PITCH + c0]);
            ah[1] = __float_as_uint(xs_hi[(r0 + 8) * XS_PITCH + c0]);
            ah[2] = __float_as_uint(xs_hi[r0 * XS_PITCH + c0 + 4]);
            ah[3] = __float_as_uint(xs_hi[(r0 + 8) * XS_PITCH + c0 + 4]);
            al[0] = __float_as_uint(xs_lo[r0 * XS_PITCH + c0]);
            al[1] = __float_as_uint(xs_lo[(r0 + 8) * XS_PITCH + c0]);
            al[2] = __float_as_uint(xs_lo[r0 * XS_PITCH + c0 + 4]);
            al[3] = __float_as_uint(xs_lo[(r0 + 8) * XS_PITCH + c0 + 4]);

            const int k8g = ch * 4 + k8l;
            const float2* bp = Bfrag_g
                + ((size_t)(k8g * NTILES + warpN * 12) * 2) * 32 + lane;
#pragma unroll
            for (int nt = 0; nt < 12; ++nt) {
                float2 bh = bp[nt * 64];
                float2 bl = bp[nt * 64 + 32];
                mma_tf32(acc[nt], ah, bh);   // hi * hi
                mma_tf32(acc[nt], al, bh);   // lo * hi
                mma_tf32(acc[nt], ah, bl);   // hi * lo
            }
        }
    }
    __syncthreads();   // stage dead; smem becomes qkv

    // scatter accumulators into padded Q/K/V smem
#pragma unroll
    for (int nt = 0; nt < 12; ++nt) {
        int n   = warpN * 96 + nt * 8 + (lane & 3) * 2;
        int mat = n >> 6;
        int h   = n & 63;
        float* base = qkv + mat * TT * QKV_PITCH;
        base[r0 * QKV_PITCH + h]           = acc[nt][0];
        base[r0 * QKV_PITCH + h + 1]       = acc[nt][1];
        base[(r0 + 8) * QKV_PITCH + h]     = acc[nt][2];
        base[(r0 + 8) * QKV_PITCH + h + 1] = acc[nt][3];
    }
    __syncthreads();

    float* qs = qkv;
    float* ks = qkv + TT * QKV_PITCH;
    float* vs = qkv + 2 * TT * QKV_PITCH;

    // ---- Phase 2: S = Q @ K^T (causal) ----
    {
        const int t  = tid >> 2;
        const int sb = (tid & 3) * 32;
        const float* qrow = qs + t * QKV_PITCH;
        for (int so = 0; so < 32; ++so) {
            int s = sb + so;
            if (s <= t) {
                const float* krow = ks + s * QKV_PITCH;
                float sum = 0.f;
#pragma unroll 16
                for (int h = 0; h < HH; ++h)
                    sum = fmaf(qrow[h], krow[h], sum);
                S[t * TT + s] = sum;
            }
        }
    }
    __syncthreads();

    // ---- Phase 3: causal softmax ----
    {
        for (int rr = 0; rr < 8; ++rr) {
            int t = warp * 8 + rr;
            float vals[4];
            float mx = -INFINITY;
#pragma unroll
            for (int j = 0; j < 4; ++j) {
                int s = lane + j * 32;
                vals[j] = (s <= t) ? S[t * TT + s] : -INFINITY;
                mx = fmaxf(mx, vals[j]);
            }
#pragma unroll
            for (int o = 16; o > 0; o >>= 1)
                mx = fmaxf(mx, __shfl_xor_sync(0xffffffffu, mx, o));
            float sum = 0.f;
#pragma unroll
            for (int j = 0; j < 4; ++j) {
                int s = lane + j * 32;
                vals[j] = (s <= t) ? __expf(vals[j] - mx) : 0.f;
                sum += vals[j];
            }
#pragma unroll
            for (int o = 16; o > 0; o >>= 1)
                sum += __shfl_xor_sync(0xffffffffu, sum, o);
            float inv = 1.f / sum;
#pragma unroll
            for (int j = 0; j < 4; ++j)
                S[t * TT + lane + j * 32] = vals[j] * inv;   // s>t -> exactly 0
        }
    }
    __syncthreads();

    // ---- Phase 4: out = S @ V ----
    {
        const int h  = tid & 63;
        const int tg = tid >> 6;
        float* ob = out + (size_t)b * TT * HH;
        for (int rr = 0; rr < 16; ++rr) {
            int t = rr * 8 + tg;
            const float* srow = S + t * TT;
            float sum = 0.f;
            for (int s = 0; s <= t; ++s)
                sum = fmaf(srow[s], vs[s * QKV_PITCH + h], sum);
            ob[t * HH + h] = sum;
        }
    }
}

extern "C" void kernel_launch(void* const* d_in, const int* in_sizes, int n_in,
                              void* d_out, int out_size)
{
    const float* x  = (const float*)d_in[0];
    const float* Wk = (const float*)d_in[1];
    const float* Wq = (const float*)d_in[2];
    const float* Wv = (const float*)d_in[3];
    float* out = (float*)d_out;

    static int smem_set = 0;
    if (!smem_set) {
        cudaFuncSetAttribute(head_attn_mma,
                             cudaFuncAttributeMaxDynamicSharedMemorySize,
                             SMEM_BYTES);
        smem_set = 1;
    }
    prep_w<<<(NK8 * NTILES * 2 * 32 + 255) / 256, 256>>>(Wk, Wq, Wv);
    head_attn_mma<<<BB, 512, SMEM_BYTES>>>(x, out);
}

// round 10
// speedup vs baseline: 1.7924x; 1.2435x over previous
#include <cuda_runtime.h>
#include <math.h>
#include <stdint.h>

// ---------------- problem constants ----------------
#define BB   1024
#define TT   128
#define CC   1024
#define HH   64
#define N3   192            // Q|K|V combined output cols

#define KCH  32             // K-chunk (floats) staged per iteration
#define NCHUNKS (CC/KCH)    // 32
#define NK8  (CC/8)         // 128 k8 groups total
#define NTILES (N3/8)       // 24 n-tiles of 8

// ---------------- smem layout (floats) ----------------
// post-projection: qs[128][65] | kt[64][132] | vs[128][66] | S[128][128]
// phase-1 staging xs_hi[128][33]+xs_lo[128][33] overlaps qs/kt head (dead by then)
#define XS_PITCH 33
#define QS_OFF   0
#define QS_PITCH 65
#define KT_OFF   (QS_OFF + TT*QS_PITCH)       // 8320
#define KT_PITCH 132
#define VS_OFF   (KT_OFF + HH*KT_PITCH)       // 16768
#define VS_PITCH 66
#define S_OFF    (VS_OFF + TT*VS_PITCH)       // 25216
#define TOTAL_FLOATS (S_OFF + TT*TT)          // 41600
#define SMEM_BYTES (TOTAL_FLOATS*4)           // 166400

// B pre-packed in m16n8k8 tf32 fragment order, hi+lo fused:
// Bfrag4[k8(128)][nt(24)][lane(32)] = float4{bh0, bh1, bl0, bl1}
//   b0: k = k8*8 + (lane&3),   n = nt*8 + (lane>>2)
//   b1: k = k8*8 + (lane&3)+4, same n
__device__ __align__(16) float4 Bfrag4_g[NK8 * NTILES * 32];

// ---------------- helpers ----------------
__device__ __forceinline__ float tf32_rnd(float x) {
    unsigned u;
    asm("cvt.rna.tf32.f32 %0, %1;" : "=r"(u) : "f"(x));
    return __uint_as_float(u);
}

__device__ __forceinline__ void mma_tf32(float* d, const unsigned* a,
                                         unsigned b0, unsigned b1) {
    asm volatile(
        "mma.sync.aligned.m16n8k8.row.col.f32.tf32.tf32.f32 "
        "{%0,%1,%2,%3}, {%4,%5,%6,%7}, {%8,%9}, {%0,%1,%2,%3};"
        : "+f"(d[0]), "+f"(d[1]), "+f"(d[2]), "+f"(d[3])
        : "r"(a[0]), "r"(a[1]), "r"(a[2]), "r"(a[3]), "r"(b0), "r"(b1));
}

// ---------------- prep kernel: pack W into fused hi/lo fragments ----------------
__global__ void prep_w(const float* __restrict__ Wk,
                       const float* __restrict__ Wq,
                       const float* __restrict__ Wv)
{
    int i = blockIdx.x * blockDim.x + threadIdx.x;   // 0 .. 98303
    if (i >= NK8 * NTILES * 32) return;
    int lane = i & 31;
    int rest = i >> 5;                // k8*24 + nt
    int nt   = rest % NTILES;
    int k8   = rest / NTILES;         // 0..127
    int n    = nt * 8 + (lane >> 2);
    int mat  = n >> 6;                // 0=Q,1=K,2=V
    int h    = n & 63;
    const float* W = (mat == 0) ? Wq : (mat == 1) ? Wk : Wv;
    int k0 = k8 * 8 + (lane & 3);
    float w0 = W[k0 * HH + h];
    float w1 = W[(k0 + 4) * HH + h];
    float h0 = tf32_rnd(w0), h1 = tf32_rnd(w1);
    float4 v;
    v.x = h0; v.y = h1;
    v.z = tf32_rnd(w0 - h0);
    v.w = tf32_rnd(w1 - h1);
    Bfrag4_g[i] = v;
}

// ---------------- main fused kernel ----------------
__global__ __launch_bounds__(512, 1)
void head_attn_mma(const float* __restrict__ x, float* __restrict__ out)
{
    extern __shared__ float data[];
    float* xs_hi = data;                       // [128][33] (phase-1 staging)
    float* xs_lo = data + TT * XS_PITCH;
    float* qs    = data + QS_OFF;              // [128][65]
    float* kt    = data + KT_OFF;              // [64][132]  (K transposed: [h][s])
    float* vs    = data + VS_OFF;              // [128][66]
    float* S     = data + S_OFF;               // [128][128]

    const int b     = blockIdx.x;
    const int tid   = threadIdx.x;
    const int warp  = tid >> 5;
    const int lane  = tid & 31;
    const int warpM = warp >> 2;    // 0..3 -> rows warpM*32 .. +31 (2 m16 blocks)
    const int warpN = warp & 3;     // 0..3 -> ntiles warpN*6 .. +5 (48 cols)
    const float* xb = x + (size_t)b * TT * CC;

    // ---- Phase 1: QKV projection, tf32 mma.sync with 3-term split ----
    float acc[2][6][4];
#pragma unroll
    for (int bk = 0; bk < 2; ++bk)
#pragma unroll
        for (int nt = 0; nt < 6; ++nt)
#pragma unroll
            for (int j = 0; j < 4; ++j) acc[bk][nt][j] = 0.f;

    // prefetch chunk 0 (2 float4 per thread)
    const int prow0 = tid >> 3,          pj40 = tid & 7;
    const int prow1 = (tid + 512) >> 3,  pj41 = (tid + 512) & 7;
    float4 pf0 = ((const float4*)(xb + (size_t)prow0 * CC))[pj40];
    float4 pf1 = ((const float4*)(xb + (size_t)prow1 * CC))[pj41];

    const int r0 = warpM * 32 + (lane >> 2);   // block0 rows r0, r0+8; block1 +16
    const int kk = lane & 3;

    for (int ch = 0; ch < NCHUNKS; ++ch) {
        __syncthreads();   // previous compute finished reading stage

        // convert + store this chunk's x into xs_hi/xs_lo
        {
            float v[4] = {pf0.x, pf0.y, pf0.z, pf0.w};
#pragma unroll
            for (int e = 0; e < 4; ++e) {
                float hi = tf32_rnd(v[e]);
                xs_hi[prow0 * XS_PITCH + pj40 * 4 + e] = hi;
                xs_lo[prow0 * XS_PITCH + pj40 * 4 + e] = tf32_rnd(v[e] - hi);
            }
            float w[4] = {pf1.x, pf1.y, pf1.z, pf1.w};
#pragma unroll
            for (int e = 0; e < 4; ++e) {
                float hi = tf32_rnd(w[e]);
                xs_hi[prow1 * XS_PITCH + pj41 * 4 + e] = hi;
                xs_lo[prow1 * XS_PITCH + pj41 * 4 + e] = tf32_rnd(w[e] - hi);
            }
        }
        // prefetch next chunk (overlaps the MMA compute below)
        if (ch + 1 < NCHUNKS) {
            int c0n = (ch + 1) * KCH;
            pf0 = ((const float4*)(xb + (size_t)prow0 * CC + c0n))[pj40];
            pf1 = ((const float4*)(xb + (size_t)prow1 * CC + c0n))[pj41];
        }
        __syncthreads();

        // compute: 4 k8-groups x (2 m-blocks x 6 n-tiles x 3 terms)
#pragma unroll
        for (int k8l = 0; k8l < 4; ++k8l) {
            const int c0 = k8l * 8 + kk;
            unsigned ah0[4], al0[4], ah1[4], al1[4];
            ah0[0] = __float_as_uint(xs_hi[r0 * XS_PITCH + c0]);
            ah0[1] = __float_as_uint(xs_hi[(r0 + 8) * XS_PITCH + c0]);
            ah0[2] = __float_as_uint(xs_hi[r0 * XS_PITCH + c0 + 4]);
            ah0[3] = __float_as_uint(xs_hi[(r0 + 8) * XS_PITCH + c0 + 4]);
            al0[0] = __float_as_uint(xs_lo[r0 * XS_PITCH + c0]);
            al0[1] = __float_as_uint(xs_lo[(r0 + 8) * XS_PITCH + c0]);
            al0[2] = __float_as_uint(xs_lo[r0 * XS_PITCH + c0 + 4]);
            al0[3] = __float_as_uint(xs_lo[(r0 + 8) * XS_PITCH + c0 + 4]);
            ah1[0] = __float_as_uint(xs_hi[(r0 + 16) * XS_PITCH + c0]);
            ah1[1] = __float_as_uint(xs_hi[(r0 + 24) * XS_PITCH + c0]);
            ah1[2] = __float_as_uint(xs_hi[(r0 + 16) * XS_PITCH + c0 + 4]);
            ah1[3] = __float_as_uint(xs_hi[(r0 + 24) * XS_PITCH + c0 + 4]);
            al1[0] = __float_as_uint(xs_lo[(r0 + 16) * XS_PITCH + c0]);
            al1[1] = __float_as_uint(xs_lo[(r0 + 24) * XS_PITCH + c0]);
            al1[2] = __float_as_uint(xs_lo[(r0 + 16) * XS_PITCH + c0 + 4]);
            al1[3] = __float_as_uint(xs_lo[(r0 + 24) * XS_PITCH + c0 + 4]);

            const int k8g = ch * 4 + k8l;
            const float4* bp = Bfrag4_g + (size_t)(k8g * NTILES + warpN * 6) * 32 + lane;
#pragma unroll
            for (int nt = 0; nt < 6; ++nt) {
                float4 b4 = bp[nt * 32];
                unsigned bh0 = __float_as_uint(b4.x), bh1 = __float_as_uint(b4.y);
                unsigned bl0 = __float_as_uint(b4.z), bl1 = __float_as_uint(b4.w);
                mma_tf32(acc[0][nt], ah0, bh0, bh1);
                mma_tf32(acc[0][nt], al0, bh0, bh1);
                mma_tf32(acc[0][nt], ah0, bl0, bl1);
                mma_tf32(acc[1][nt], ah1, bh0, bh1);
                mma_tf32(acc[1][nt], al1, bh0, bh1);
                mma_tf32(acc[1][nt], ah1, bl0, bl1);
            }
        }
    }
    __syncthreads();   // stage dead; smem becomes qs/kt/vs

    // scatter accumulators: Q -> qs[r][h], K -> kt[h][s], V -> vs[s][h]
#pragma unroll
    for (int bk = 0; bk < 2; ++bk) {
#pragma unroll
        for (int nt = 0; nt < 6; ++nt) {
            int r   = warpM * 32 + bk * 16 + (lane >> 2);
            int n   = warpN * 48 + nt * 8 + (lane & 3) * 2;
            int mat = n >> 6;
            int h   = n & 63;
            float v0 = acc[bk][nt][0], v1 = acc[bk][nt][1];
            float v2 = acc[bk][nt][2], v3 = acc[bk][nt][3];
            if (mat == 0) {
                qs[r * QS_PITCH + h]           = v0;
                qs[r * QS_PITCH + h + 1]       = v1;
                qs[(r + 8) * QS_PITCH + h]     = v2;
                qs[(r + 8) * QS_PITCH + h + 1] = v3;
            } else if (mat == 1) {
                kt[h * KT_PITCH + r]           = v0;
                kt[(h + 1) * KT_PITCH + r]     = v1;
                kt[h * KT_PITCH + r + 8]       = v2;
                kt[(h + 1) * KT_PITCH + r + 8] = v3;
            } else {
                vs[r * VS_PITCH + h]           = v0;
                vs[r * VS_PITCH + h + 1]       = v1;
                vs[(r + 8) * VS_PITCH + h]     = v2;
                vs[(r + 8) * VS_PITCH + h + 1] = v3;
            }
        }
    }
    __syncthreads();

    // ---- Phase 2: S = Q @ K^T (causal), 4t x 8s register blocking ----
    {
        const int tb = tid >> 4;          // 0..31 -> t0 = tb*4
        const int sb = tid & 15;          // 0..15 -> s0 = sb*8
        const int t0 = tb * 4, s0 = sb * 8;
        if (s0 <= t0 + 3) {
            float a[4][8];
#pragma unroll
            for (int i = 0; i < 4; ++i)
#pragma unroll
                for (int j = 0; j < 8; ++j) a[i][j] = 0.f;
#pragma unroll 4
            for (int h = 0; h < HH; ++h) {
                float q0 = qs[(t0 + 0) * QS_PITCH + h];
                float q1 = qs[(t0 + 1) * QS_PITCH + h];
                float q2 = qs[(t0 + 2) * QS_PITCH + h];
                float q3 = qs[(t0 + 3) * QS_PITCH + h];
                float4 k4a = *(const float4*)&kt[h * KT_PITCH + s0];
                float4 k4b = *(const float4*)&kt[h * KT_PITCH + s0 + 4];
                float kv[8] = {k4a.x, k4a.y, k4a.z, k4a.w,
                               k4b.x, k4b.y, k4b.z, k4b.w};
#pragma unroll
                for (int j = 0; j < 8; ++j) {
                    a[0][j] = fmaf(q0, kv[j], a[0][j]);
                    a[1][j] = fmaf(q1, kv[j], a[1][j]);
                    a[2][j] = fmaf(q2, kv[j], a[2][j]);
                    a[3][j] = fmaf(q3, kv[j], a[3][j]);
                }
            }
#pragma unroll
            for (int i = 0; i < 4; ++i)
#pragma unroll
                for (int j = 0; j < 8; ++j)
                    S[(t0 + i) * TT + s0 + j] = a[i][j];
        }
    }
    __syncthreads();

    // ---- Phase 3: causal softmax (warp per 8 rows) ----
    {
        for (int rr = 0; rr < 8; ++rr) {
            int t = warp * 8 + rr;
            float vals[4];
            float mx = -INFINITY;
#pragma unroll
            for (int j = 0; j < 4; ++j) {
                int s = lane + j * 32;
                vals[j] = (s <= t) ? S[t * TT + s] : -INFINITY;
                mx = fmaxf(mx, vals[j]);
            }
#pragma unroll
            for (int o = 16; o > 0; o >>= 1)
                mx = fmaxf(mx, __shfl_xor_sync(0xffffffffu, mx, o));
            float sum = 0.f;
#pragma unroll
            for (int j = 0; j < 4; ++j) {
                int s = lane + j * 32;
                vals[j] = (s <= t) ? __expf(vals[j] - mx) : 0.f;
                sum += vals[j];
            }
#pragma unroll
            for (int o = 16; o > 0; o >>= 1)
                sum += __shfl_xor_sync(0xffffffffu, sum, o);
            float inv = 1.f / sum;
#pragma unroll
            for (int j = 0; j < 4; ++j)
                S[t * TT + lane + j * 32] = vals[j] * inv;   // s>t -> exactly 0
        }
    }
    __syncthreads();

    // ---- Phase 4: out = S @ V, 8t x 2h register blocking ----
    {
        const int h0 = lane * 2;           // lane covers h0, h0+1
        const int t0 = warp * 8;           // warp covers t0..t0+7
        float o0[8], o1[8];
#pragma unroll
        for (int i = 0; i < 8; ++i) { o0[i] = 0.f; o1[i] = 0.f; }
        const int smax = t0 + 7;           // S[t][s>t]==0 exactly -> safe
        for (int s = 0; s <= smax; ++s) {
            float2 v2 = *(const float2*)&vs[s * VS_PITCH + h0];
#pragma unroll
            for (int i = 0; i < 8; ++i) {
                float sv = S[(t0 + i) * TT + s];
                o0[i] = fmaf(sv, v2.x, o0[i]);
                o1[i] = fmaf(sv, v2.y, o1[i]);
            }
        }
        float* ob = out + (size_t)b * TT * HH;
#pragma unroll
        for (int i = 0; i < 8; ++i) {
            float2 r; r.x = o0[i]; r.y = o1[i];
            *(float2*)&ob[(t0 + i) * HH + h0] = r;
        }
    }
}

extern "C" void kernel_launch(void* const* d_in, const int* in_sizes, int n_in,
                              void* d_out, int out_size)
{
    const float* x  = (const float*)d_in[0];
    const float* Wk = (const float*)d_in[1];
    const float* Wq = (const float*)d_in[2];
    const float* Wv = (const float*)d_in[3];
    float* out = (float*)d_out;

    static int smem_set = 0;
    if (!smem_set) {
        cudaFuncSetAttribute(head_attn_mma,
                             cudaFuncAttributeMaxDynamicSharedMemorySize,
                             SMEM_BYTES);
        smem_set = 1;
    }
    prep_w<<<(NK8 * NTILES * 32 + 255) / 256, 256>>>(Wk, Wq, Wv);
    head_attn_mma<<<BB, 512, SMEM_BYTES>>>(x, out);
}

// round 11
// speedup vs baseline: 3.4734x; 1.9379x over previous
#include <cuda_runtime.h>
#include <cuda_bf16.h>
#include <math.h>
#include <stdint.h>

// ---------------- problem constants ----------------
#define BB   1024
#define TT   128
#define CC   1024
#define HH   64
#define N3   192            // Q|K|V combined output cols

#define KCH  32             // K-chunk (floats) staged per iteration
#define NCHUNKS (CC/KCH)    // 32
#define NK16 (CC/16)        // 64 k16 groups total
#define NTILES (N3/8)       // 24 n-tiles of 8

// ---------------- smem layout (floats) ----------------
// post-projection: qs[128][65] | kt[64][132] | vs[128][66] | S[128][128]
// phase-1 staging (2 buffers x (hi[128][20] + lo[128][20]) uint32) overlaps qs/kt
#define XS_PITCH 20
#define XS_BUF_U32 (2*TT*XS_PITCH)            // 5120 per buffer (hi+lo)
#define QS_OFF   0
#define QS_PITCH 65
#define KT_OFF   (QS_OFF + TT*QS_PITCH)       // 8320
#define KT_PITCH 132
#define VS_OFF   (KT_OFF + HH*KT_PITCH)       // 16768
#define VS_PITCH 66
#define S_OFF    (VS_OFF + TT*VS_PITCH)       // 25216
#define TOTAL_FLOATS (S_OFF + TT*TT)          // 41600
#define SMEM_BYTES (TOTAL_FLOATS*4)           // 166400

// B pre-packed in m16n8k16 bf16 fragment order, hi+lo fused:
// Bfrag[k16(64)][nt(24)][lane(32)] = uint4{b0_hi, b1_hi, b0_lo, b1_lo}
//   b0: k = k16*16 + 2*(lane&3) (+1 in high half), n = nt*8 + (lane>>2)
//   b1: k = k16*16 + 2*(lane&3)+8 (+1),           same n
__device__ __align__(16) uint4 Bfrag_g[NK16 * NTILES * 32];

// ---------------- helpers ----------------
__device__ __forceinline__ void split2(float a, float b, unsigned& hi, unsigned& lo) {
    __nv_bfloat16 ha = __float2bfloat16_rn(a);
    __nv_bfloat16 hb = __float2bfloat16_rn(b);
    float ra = a - __bfloat162float(ha);
    float rb = b - __bfloat162float(hb);
    __nv_bfloat16 la = __float2bfloat16_rn(ra);
    __nv_bfloat16 lb = __float2bfloat16_rn(rb);
    hi = ((unsigned)__bfloat16_as_ushort(hb) << 16) | __bfloat16_as_ushort(ha);
    lo = ((unsigned)__bfloat16_as_ushort(lb) << 16) | __bfloat16_as_ushort(la);
}

__device__ __forceinline__ void mma_bf16(float* d, const unsigned* a,
                                         unsigned b0, unsigned b1) {
    asm volatile(
        "mma.sync.aligned.m16n8k16.row.col.f32.bf16.bf16.f32 "
        "{%0,%1,%2,%3}, {%4,%5,%6,%7}, {%8,%9}, {%0,%1,%2,%3};"
        : "+f"(d[0]), "+f"(d[1]), "+f"(d[2]), "+f"(d[3])
        : "r"(a[0]), "r"(a[1]), "r"(a[2]), "r"(a[3]), "r"(b0), "r"(b1));
}

// ---------------- prep kernel: pack W into fused bf16 hi/lo fragments ----------------
__global__ void prep_w(const float* __restrict__ Wk,
                       const float* __restrict__ Wq,
                       const float* __restrict__ Wv)
{
    int i = blockIdx.x * blockDim.x + threadIdx.x;   // 0 .. 49151
    if (i >= NK16 * NTILES * 32) return;
    int lane = i & 31;
    int rest = i >> 5;                // k16*24 + nt
    int nt   = rest % NTILES;
    int k16  = rest / NTILES;         // 0..63
    int n    = nt * 8 + (lane >> 2);
    int mat  = n >> 6;                // 0=Q,1=K,2=V
    int h    = n & 63;
    const float* W = (mat == 0) ? Wq : (mat == 1) ? Wk : Wv;
    int kb = k16 * 16 + 2 * (lane & 3);
    float w00 = W[kb * HH + h];
    float w01 = W[(kb + 1) * HH + h];
    float w10 = W[(kb + 8) * HH + h];
    float w11 = W[(kb + 9) * HH + h];
    uint4 v;
    split2(w00, w01, v.x, v.z);
    split2(w10, w11, v.y, v.w);
    Bfrag_g[i] = v;
}

// ---------------- main fused kernel ----------------
__global__ __launch_bounds__(512, 1)
void head_attn_mma(const float* __restrict__ x, float* __restrict__ out)
{
    extern __shared__ float data[];
    float* qs = data + QS_OFF;               // [128][65]
    float* kt = data + KT_OFF;               // [64][132]  (K transposed: [h][s])
    float* vs = data + VS_OFF;               // [128][66]
    float* S  = data + S_OFF;                // [128][128]
    unsigned* xsb = (unsigned*)data;         // staging: 2 x (hi[128][20] | lo[128][20])

    const int b     = blockIdx.x;
    const int tid   = threadIdx.x;
    const int warp  = tid >> 5;
    const int lane  = tid & 31;
    const int warpM = warp >> 2;    // 0..3 -> rows warpM*32 .. +31 (2 m16 blocks)
    const int warpN = warp & 3;     // 0..3 -> ntiles warpN*6 .. +5 (48 cols)
    const float* xb = x + (size_t)b * TT * CC;

    // ---- Phase 1: QKV projection, bf16 m16n8k16 with 3-term split ----
    float acc[2][6][4];
#pragma unroll
    for (int bk = 0; bk < 2; ++bk)
#pragma unroll
        for (int nt = 0; nt < 6; ++nt)
#pragma unroll
            for (int j = 0; j < 4; ++j) acc[bk][nt][j] = 0.f;

    // each thread stages 2 float4 = 8 floats = pairs p0..p0+1 per float4
    const int prow0 = tid >> 3,          pj40 = tid & 7;
    const int prow1 = (tid + 512) >> 3,  pj41 = (tid + 512) & 7;
    float4 pf0 = ((const float4*)(xb + (size_t)prow0 * CC))[pj40];
    float4 pf1 = ((const float4*)(xb + (size_t)prow1 * CC))[pj41];

    const int r0 = warpM * 32 + (lane >> 2);   // block0 rows r0, r0+8; block1 +16
    const int kk = lane & 3;                   // pair index within k16 group

    // store chunk 0 into buffer 0
    {
        unsigned* hi0 = xsb;                // buffer 0
        unsigned* lo0 = xsb + TT * XS_PITCH;
        unsigned h, l;
        split2(pf0.x, pf0.y, h, l);
        hi0[prow0 * XS_PITCH + pj40 * 2]     = h; lo0[prow0 * XS_PITCH + pj40 * 2]     = l;
        split2(pf0.z, pf0.w, h, l);
        hi0[prow0 * XS_PITCH + pj40 * 2 + 1] = h; lo0[prow0 * XS_PITCH + pj40 * 2 + 1] = l;
        split2(pf1.x, pf1.y, h, l);
        hi0[prow1 * XS_PITCH + pj41 * 2]     = h; lo0[prow1 * XS_PITCH + pj41 * 2]     = l;
        split2(pf1.z, pf1.w, h, l);
        hi0[prow1 * XS_PITCH + pj41 * 2 + 1] = h; lo0[prow1 * XS_PITCH + pj41 * 2 + 1] = l;
    }
    // prefetch chunk 1
    pf0 = ((const float4*)(xb + (size_t)prow0 * CC + KCH))[pj40];
    pf1 = ((const float4*)(xb + (size_t)prow1 * CC + KCH))[pj41];
    __syncthreads();

    for (int ch = 0; ch < NCHUNKS; ++ch) {
        // store next chunk into the other buffer (prev compute of that buffer
        // finished before the barrier that ended iteration ch-1)
        if (ch + 1 < NCHUNKS) {
            unsigned* hin = xsb + ((ch + 1) & 1) * XS_BUF_U32;
            unsigned* lon = hin + TT * XS_PITCH;
            unsigned h, l;
            split2(pf0.x, pf0.y, h, l);
            hin[prow0 * XS_PITCH + pj40 * 2]     = h; lon[prow0 * XS_PITCH + pj40 * 2]     = l;
            split2(pf0.z, pf0.w, h, l);
            hin[prow0 * XS_PITCH + pj40 * 2 + 1] = h; lon[prow0 * XS_PITCH + pj40 * 2 + 1] = l;
            split2(pf1.x, pf1.y, h, l);
            hin[prow1 * XS_PITCH + pj41 * 2]     = h; lon[prow1 * XS_PITCH + pj41 * 2]     = l;
            split2(pf1.z, pf1.w, h, l);
            hin[prow1 * XS_PITCH + pj41 * 2 + 1] = h; lon[prow1 * XS_PITCH + pj41 * 2 + 1] = l;
        }
        if (ch + 2 < NCHUNKS) {
            int c0n = (ch + 2) * KCH;
            pf0 = ((const float4*)(xb + (size_t)prow0 * CC + c0n))[pj40];
            pf1 = ((const float4*)(xb + (size_t)prow1 * CC + c0n))[pj41];
        }

        // compute chunk ch from buffer ch&1: 2 k16 groups x 6 nt x (2 mblk x 3 terms)
        const unsigned* hic = xsb + (ch & 1) * XS_BUF_U32;
        const unsigned* loc = hic + TT * XS_PITCH;
#pragma unroll
        for (int g = 0; g < 2; ++g) {
            const int pa = g * 8 + kk;
            unsigned ah0[4], al0[4], ah1[4], al1[4];
            ah0[0] = hic[r0 * XS_PITCH + pa];
            ah0[1] = hic[(r0 + 8) * XS_PITCH + pa];
            ah0[2] = hic[r0 * XS_PITCH + pa + 4];
            ah0[3] = hic[(r0 + 8) * XS_PITCH + pa + 4];
            al0[0] = loc[r0 * XS_PITCH + pa];
            al0[1] = loc[(r0 + 8) * XS_PITCH + pa];
            al0[2] = loc[r0 * XS_PITCH + pa + 4];
            al0[3] = loc[(r0 + 8) * XS_PITCH + pa + 4];
            ah1[0] = hic[(r0 + 16) * XS_PITCH + pa];
            ah1[1] = hic[(r0 + 24) * XS_PITCH + pa];
            ah1[2] = hic[(r0 + 16) * XS_PITCH + pa + 4];
            ah1[3] = hic[(r0 + 24) * XS_PITCH + pa + 4];
            al1[0] = loc[(r0 + 16) * XS_PITCH + pa];
            al1[1] = loc[(r0 + 24) * XS_PITCH + pa];
            al1[2] = loc[(r0 + 16) * XS_PITCH + pa + 4];
            al1[3] = loc[(r0 + 24) * XS_PITCH + pa + 4];

            const int k16g = ch * 2 + g;
            const uint4* bp = Bfrag_g + (size_t)(k16g * NTILES + warpN * 6) * 32 + lane;
#pragma unroll
            for (int nt = 0; nt < 6; ++nt) {
                uint4 b4 = bp[nt * 32];
                mma_bf16(acc[0][nt], ah0, b4.x, b4.y);   // hi*hi
                mma_bf16(acc[0][nt], al0, b4.x, b4.y);   // lo*hi
                mma_bf16(acc[0][nt], ah0, b4.z, b4.w);   // hi*lo
                mma_bf16(acc[1][nt], ah1, b4.x, b4.y);
                mma_bf16(acc[1][nt], al1, b4.x, b4.y);
                mma_bf16(acc[1][nt], ah1, b4.z, b4.w);
            }
        }
        __syncthreads();
    }

    // scatter accumulators: Q -> qs[r][h], K -> kt[h][s], V -> vs[s][h]
#pragma unroll
    for (int bk = 0; bk < 2; ++bk) {
#pragma unroll
        for (int nt = 0; nt < 6; ++nt) {
            int r   = warpM * 32 + bk * 16 + (lane >> 2);
            int n   = warpN * 48 + nt * 8 + (lane & 3) * 2;
            int mat = n >> 6;
            int h   = n & 63;
            float v0 = acc[bk][nt][0], v1 = acc[bk][nt][1];
            float v2 = acc[bk][nt][2], v3 = acc[bk][nt][3];
            if (mat == 0) {
                qs[r * QS_PITCH + h]           = v0;
                qs[r * QS_PITCH + h + 1]       = v1;
                qs[(r + 8) * QS_PITCH + h]     = v2;
                qs[(r + 8) * QS_PITCH + h + 1] = v3;
            } else if (mat == 1) {
                kt[h * KT_PITCH + r]           = v0;
                kt[(h + 1) * KT_PITCH + r]     = v1;
                kt[h * KT_PITCH + r + 8]       = v2;
                kt[(h + 1) * KT_PITCH + r + 8] = v3;
            } else {
                vs[r * VS_PITCH + h]           = v0;
                vs[r * VS_PITCH + h + 1]       = v1;
                vs[(r + 8) * VS_PITCH + h]     = v2;
                vs[(r + 8) * VS_PITCH + h + 1] = v3;
            }
        }
    }
    __syncthreads();

    // ---- Phase 2: S = Q @ K^T (causal), 4t x 8s register blocking ----
    {
        const int tb = tid >> 4;          // 0..31 -> t0 = tb*4
        const int sb = tid & 15;          // 0..15 -> s0 = sb*8
        const int t0 = tb * 4, s0 = sb * 8;
        if (s0 <= t0 + 3) {
            float a[4][8];
#pragma unroll
            for (int i = 0; i < 4; ++i)
#pragma unroll
                for (int j = 0; j < 8; ++j) a[i][j] = 0.f;
#pragma unroll 4
            for (int h = 0; h < HH; ++h) {
                float q0 = qs[(t0 + 0) * QS_PITCH + h];
                float q1 = qs[(t0 + 1) * QS_PITCH + h];
                float q2 = qs[(t0 + 2) * QS_PITCH + h];
                float q3 = qs[(t0 + 3) * QS_PITCH + h];
                float4 k4a = *(const float4*)&kt[h * KT_PITCH + s0];
                float4 k4b = *(const float4*)&kt[h * KT_PITCH + s0 + 4];
                float kv[8] = {k4a.x, k4a.y, k4a.z, k4a.w,
                               k4b.x, k4b.y, k4b.z, k4b.w};
#pragma unroll
                for (int j = 0; j < 8; ++j) {
                    a[0][j] = fmaf(q0, kv[j], a[0][j]);
                    a[1][j] = fmaf(q1, kv[j], a[1][j]);
                    a[2][j] = fmaf(q2, kv[j], a[2][j]);
                    a[3][j] = fmaf(q3, kv[j], a[3][j]);
                }
            }
#pragma unroll
            for (int i = 0; i < 4; ++i)
#pragma unroll
                for (int j = 0; j < 8; ++j)
                    S[(t0 + i) * TT + s0 + j] = a[i][j];
        }
    }
    __syncthreads();

    // ---- Phase 3: causal softmax (warp per 8 rows) ----
    {
        for (int rr = 0; rr < 8; ++rr) {
            int t = warp * 8 + rr;
            float vals[4];
            float mx = -INFINITY;
#pragma unroll
            for (int j = 0; j < 4; ++j) {
                int s = lane + j * 32;
                vals[j] = (s <= t) ? S[t * TT + s] : -INFINITY;
                mx = fmaxf(mx, vals[j]);
            }
#pragma unroll
            for (int o = 16; o > 0; o >>= 1)
                mx = fmaxf(mx, __shfl_xor_sync(0xffffffffu, mx, o));
            float sum = 0.f;
#pragma unroll
            for (int j = 0; j < 4; ++j) {
                int s = lane + j * 32;
                vals[j] = (s <= t) ? __expf(vals[j] - mx) : 0.f;
                sum += vals[j];
            }
#pragma unroll
            for (int o = 16; o > 0; o >>= 1)
                sum += __shfl_xor_sync(0xffffffffu, sum, o);
            float inv = 1.f / sum;
#pragma unroll
            for (int j = 0; j < 4; ++j)
                S[t * TT + lane + j * 32] = vals[j] * inv;   // s>t -> exactly 0
        }
    }
    __syncthreads();

    // ---- Phase 4: out = S @ V, 8t x 2h register blocking ----
    {
        const int h0 = lane * 2;           // lane covers h0, h0+1
        const int t0 = warp * 8;           // warp covers t0..t0+7
        float o0[8], o1[8];
#pragma unroll
        for (int i = 0; i < 8; ++i) { o0[i] = 0.f; o1[i] = 0.f; }
        const int smax = t0 + 7;           // S[t][s>t]==0 exactly -> safe
        for (int s = 0; s <= smax; ++s) {
            float2 v2 = *(const float2*)&vs[s * VS_PITCH + h0];
#pragma unroll
            for (int i = 0; i < 8; ++i) {
                float sv = S[(t0 + i) * TT + s];
                o0[i] = fmaf(sv, v2.x, o0[i]);
                o1[i] = fmaf(sv, v2.y, o1[i]);
            }
        }
        float* ob = out + (size_t)b * TT * HH;
#pragma unroll
        for (int i = 0; i < 8; ++i) {
            float2 r; r.x = o0[i]; r.y = o1[i];
            *(float2*)&ob[(t0 + i) * HH + h0] = r;
        }
    }
}

extern "C" void kernel_launch(void* const* d_in, const int* in_sizes, int n_in,
                              void* d_out, int out_size)
{
    const float* x  = (const float*)d_in[0];
    const float* Wk = (const float*)d_in[1];
    const float* Wq = (const float*)d_in[2];
    const float* Wv = (const float*)d_in[3];
    float* out = (float*)d_out;

    static int smem_set = 0;
    if (!smem_set) {
        cudaFuncSetAttribute(head_attn_mma,
                             cudaFuncAttributeMaxDynamicSharedMemorySize,
                             SMEM_BYTES);
        smem_set = 1;
    }
    prep_w<<<(NK16 * NTILES * 32 + 255) / 256, 256>>>(Wk, Wq, Wv);
    head_attn_mma<<<BB, 512, SMEM_BYTES>>>(x, out);
}

// round 12
// speedup vs baseline: 3.7563x; 1.0814x over previous
#include <cuda_runtime.h>
#include <cuda_bf16.h>
#include <math.h>
#include <stdint.h>

// ---------------- problem constants ----------------
#define BB   1024
#define TT   128
#define CC   1024
#define HH   64
#define N3   192
#define KCH  32
#define NCHUNKS (CC/KCH)    // 32
#define NK16 (CC/16)        // 64
#define NTILES (N3/8)       // 24

// ---------------- smem layout (byte offsets) ----------------
// staging (phase 1): 2 buffers x (hi[128][20]u32 | lo[128][20]u32) @0 (40960 B)
// q_hi/q_lo/k_hi/k_lo: [128][72] bf16 (pitch 144 B)  -> written at scatter
// vt_hi/vt_lo: [64][136] bf16 (pitch 272 B)
// S: [128][128] fp32
// p_hi/p_lo: [128][136] bf16 (overlaps q/k; live from phase 3)
#define XS_PITCH   20
#define XS_BUF_U32 (2*TT*XS_PITCH)     // 5120 u32 = 20480 B per buffer
#define STAGE_B    20480
#define Q_HI_B   0
#define Q_LO_B   18432
#define K_HI_B   36864
#define K_LO_B   55296
#define VT_HI_B  73728
#define VT_LO_B  91136
#define S_B      108544
#define P_HI_B   0
#define P_LO_B   34816
#define SMEM_BYTES 174080
#define QK_PITCH_B 144
#define VT_PITCH_B 272
#define P_PITCH_B  272

// B pre-packed in m16n8k16 bf16 fragment order, hi+lo fused (unchanged from R10)
__device__ __align__(16) uint4 Bfrag_g[NK16 * NTILES * 32];

// phase-2 tile list: (tb, st) with st <= 2*tb+1  (72 pairs, equal cost)
__device__ const unsigned char TB72[72] = {
    0,0, 1,1,1,1, 2,2,2,2,2,2, 3,3,3,3,3,3,3,3,
    4,4,4,4,4,4,4,4,4,4, 5,5,5,5,5,5,5,5,5,5,5,5,
    6,6,6,6,6,6,6,6,6,6,6,6,6,6, 7,7,7,7,7,7,7,7,7,7,7,7,7,7,7,7};
__device__ const unsigned char ST72[72] = {
    0,1, 0,1,2,3, 0,1,2,3,4,5, 0,1,2,3,4,5,6,7,
    0,1,2,3,4,5,6,7,8,9, 0,1,2,3,4,5,6,7,8,9,10,11,
    0,1,2,3,4,5,6,7,8,9,10,11,12,13, 0,1,2,3,4,5,6,7,8,9,10,11,12,13,14,15};

// ---------------- helpers ----------------
__device__ __forceinline__ uint32_t smem_u32(const void* p) {
    uint32_t a;
    asm("{ .reg .u64 t; cvta.to.shared.u64 t, %1; cvt.u32.u64 %0, t; }" : "=r"(a) : "l"(p));
    return a;
}
__device__ __forceinline__ void split2(float a, float b, unsigned& hi, unsigned& lo) {
    __nv_bfloat16 ha = __float2bfloat16_rn(a);
    __nv_bfloat16 hb = __float2bfloat16_rn(b);
    float ra = a - __bfloat162float(ha);
    float rb = b - __bfloat162float(hb);
    __nv_bfloat16 la = __float2bfloat16_rn(ra);
    __nv_bfloat16 lb = __float2bfloat16_rn(rb);
    hi = ((unsigned)__bfloat16_as_ushort(hb) << 16) | __bfloat16_as_ushort(ha);
    lo = ((unsigned)__bfloat16_as_ushort(lb) << 16) | __bfloat16_as_ushort(la);
}
__device__ __forceinline__ void mma_bf16(float* d, const unsigned* a,
                                         unsigned b0, unsigned b1) {
    asm volatile(
        "mma.sync.aligned.m16n8k16.row.col.f32.bf16.bf16.f32 "
        "{%0,%1,%2,%3}, {%4,%5,%6,%7}, {%8,%9}, {%0,%1,%2,%3};"
        : "+f"(d[0]), "+f"(d[1]), "+f"(d[2]), "+f"(d[3])
        : "r"(a[0]), "r"(a[1]), "r"(a[2]), "r"(a[3]), "r"(b0), "r"(b1));
}
#define LDMX4(r, addr) asm volatile( \
    "ldmatrix.sync.aligned.m8n8.x4.shared.b16 {%0,%1,%2,%3}, [%4];" \
    : "=r"((r)[0]), "=r"((r)[1]), "=r"((r)[2]), "=r"((r)[3]) : "r"(addr))
#define LDMX2(r, addr) asm volatile( \
    "ldmatrix.sync.aligned.m8n8.x2.shared.b16 {%0,%1}, [%2];" \
    : "=r"((r)[0]), "=r"((r)[1]) : "r"(addr))

// ---------------- prep kernel (unchanged from R10) ----------------
__global__ void prep_w(const float* __restrict__ Wk,
                       const float* __restrict__ Wq,
                       const float* __restrict__ Wv)
{
    int i = blockIdx.x * blockDim.x + threadIdx.x;
    if (i >= NK16 * NTILES * 32) return;
    int lane = i & 31;
    int rest = i >> 5;
    int nt   = rest % NTILES;
    int k16  = rest / NTILES;
    int n    = nt * 8 + (lane >> 2);
    int mat  = n >> 6;
    int h    = n & 63;
    const float* W = (mat == 0) ? Wq : (mat == 1) ? Wk : Wv;
    int kb = k16 * 16 + 2 * (lane & 3);
    float w00 = W[kb * HH + h];
    float w01 = W[(kb + 1) * HH + h];
    float w10 = W[(kb + 8) * HH + h];
    float w11 = W[(kb + 9) * HH + h];
    uint4 v;
    split2(w00, w01, v.x, v.z);
    split2(w10, w11, v.y, v.w);
    Bfrag_g[i] = v;
}

// ---------------- main fused kernel ----------------
__global__ __launch_bounds__(512, 1)
void head_attn_mma(const float* __restrict__ x, float* __restrict__ out)
{
    extern __shared__ float data[];
    const uint32_t smb = smem_u32(data);
    float* S = (float*)((char*)data + S_B);
    unsigned* xsb = (unsigned*)data;

    const int b     = blockIdx.x;
    const int tid   = threadIdx.x;
    const int warp  = tid >> 5;
    const int lane  = tid & 31;
    const int warpM = warp >> 2;
    const int warpN = warp & 3;
    const float* xb = x + (size_t)b * TT * CC;

    // ---- Phase 1: QKV projection (bf16 m16n8k16, 3-term split) ----
    float acc[2][6][4];
#pragma unroll
    for (int bk = 0; bk < 2; ++bk)
#pragma unroll
        for (int nt = 0; nt < 6; ++nt)
#pragma unroll
            for (int j = 0; j < 4; ++j) acc[bk][nt][j] = 0.f;

    const int prow0 = tid >> 3,          pj40 = tid & 7;
    const int prow1 = (tid + 512) >> 3,  pj41 = (tid + 512) & 7;
    float4 pf0 = ((const float4*)(xb + (size_t)prow0 * CC))[pj40];
    float4 pf1 = ((const float4*)(xb + (size_t)prow1 * CC))[pj41];

    // store chunk 0 into buffer 0
    {
        unsigned* hi0 = xsb;
        unsigned* lo0 = xsb + TT * XS_PITCH;
        unsigned h, l;
        split2(pf0.x, pf0.y, h, l);
        hi0[prow0 * XS_PITCH + pj40 * 2]     = h; lo0[prow0 * XS_PITCH + pj40 * 2]     = l;
        split2(pf0.z, pf0.w, h, l);
        hi0[prow0 * XS_PITCH + pj40 * 2 + 1] = h; lo0[prow0 * XS_PITCH + pj40 * 2 + 1] = l;
        split2(pf1.x, pf1.y, h, l);
        hi0[prow1 * XS_PITCH + pj41 * 2]     = h; lo0[prow1 * XS_PITCH + pj41 * 2]     = l;
        split2(pf1.z, pf1.w, h, l);
        hi0[prow1 * XS_PITCH + pj41 * 2 + 1] = h; lo0[prow1 * XS_PITCH + pj41 * 2 + 1] = l;
    }
    pf0 = ((const float4*)(xb + (size_t)prow0 * CC + KCH))[pj40];
    pf1 = ((const float4*)(xb + (size_t)prow1 * CC + KCH))[pj41];
    __syncthreads();

    // ldmatrix A address pieces: rows warpM*32 + (lane&15) (+16 for bk1),
    // k-half (lane>>4)*16 bytes within the 32B k16-group
    const unsigned a_off = (unsigned)((warpM * 32 + (lane & 15)) * 80 + (lane >> 4) * 16);

    for (int ch = 0; ch < NCHUNKS; ++ch) {
        if (ch + 1 < NCHUNKS) {
            unsigned* hin = xsb + ((ch + 1) & 1) * XS_BUF_U32;
            unsigned* lon = hin + TT * XS_PITCH;
            unsigned h, l;
            split2(pf0.x, pf0.y, h, l);
            hin[prow0 * XS_PITCH + pj40 * 2]     = h; lon[prow0 * XS_PITCH + pj40 * 2]     = l;
            split2(pf0.z, pf0.w, h, l);
            hin[prow0 * XS_PITCH + pj40 * 2 + 1] = h; lon[prow0 * XS_PITCH + pj40 * 2 + 1] = l;
            split2(pf1.x, pf1.y, h, l);
            hin[prow1 * XS_PITCH + pj41 * 2]     = h; lon[prow1 * XS_PITCH + pj41 * 2]     = l;
            split2(pf1.z, pf1.w, h, l);
            hin[prow1 * XS_PITCH + pj41 * 2 + 1] = h; lon[prow1 * XS_PITCH + pj41 * 2 + 1] = l;
        }
        if (ch + 2 < NCHUNKS) {
            int c0n = (ch + 2) * KCH;
            pf0 = ((const float4*)(xb + (size_t)prow0 * CC + c0n))[pj40];
            pf1 = ((const float4*)(xb + (size_t)prow1 * CC + c0n))[pj41];
        }

        const unsigned hib = smb + (unsigned)((ch & 1) * STAGE_B);
        const unsigned lob = hib + TT * XS_PITCH * 4;
#pragma unroll
        for (int g = 0; g < 2; ++g) {
            unsigned ah0[4], al0[4], ah1[4], al1[4];
            unsigned ad = hib + a_off + g * 32;
            unsigned al_ = lob + a_off + g * 32;
            LDMX4(ah0, ad);
            LDMX4(al0, al_);
            LDMX4(ah1, ad + 16 * 80);
            LDMX4(al1, al_ + 16 * 80);

            const int k16g = ch * 2 + g;
            const uint4* bp = Bfrag_g + (size_t)(k16g * NTILES + warpN * 6) * 32 + lane;
#pragma unroll
            for (int nt = 0; nt < 6; ++nt) {
                uint4 b4 = bp[nt * 32];
                mma_bf16(acc[0][nt], ah0, b4.x, b4.y);
                mma_bf16(acc[0][nt], al0, b4.x, b4.y);
                mma_bf16(acc[0][nt], ah0, b4.z, b4.w);
                mma_bf16(acc[1][nt], ah1, b4.x, b4.y);
                mma_bf16(acc[1][nt], al1, b4.x, b4.y);
                mma_bf16(acc[1][nt], ah1, b4.z, b4.w);
            }
        }
        __syncthreads();
    }

    // ---- scatter: Q/K -> bf16 hi/lo rows; V -> vt[h][s] bf16 hi/lo ----
    {
        char* base = (char*)data;
#pragma unroll
        for (int bk = 0; bk < 2; ++bk) {
#pragma unroll
            for (int nt = 0; nt < 6; ++nt) {
                int r   = warpM * 32 + bk * 16 + (lane >> 2);
                int n   = warpN * 48 + nt * 8 + (lane & 3) * 2;
                int mat = n >> 6;
                int h   = n & 63;
                unsigned hiA, loA, hiB, loB;
                split2(acc[bk][nt][0], acc[bk][nt][1], hiA, loA);   // row r
                split2(acc[bk][nt][2], acc[bk][nt][3], hiB, loB);   // row r+8
                if (mat == 0) {
                    *(unsigned*)(base + Q_HI_B + r * QK_PITCH_B + h * 2)       = hiA;
                    *(unsigned*)(base + Q_LO_B + r * QK_PITCH_B + h * 2)       = loA;
                    *(unsigned*)(base + Q_HI_B + (r + 8) * QK_PITCH_B + h * 2) = hiB;
                    *(unsigned*)(base + Q_LO_B + (r + 8) * QK_PITCH_B + h * 2) = loB;
                } else if (mat == 1) {
                    *(unsigned*)(base + K_HI_B + r * QK_PITCH_B + h * 2)       = hiA;
                    *(unsigned*)(base + K_LO_B + r * QK_PITCH_B + h * 2)       = loA;
                    *(unsigned*)(base + K_HI_B + (r + 8) * QK_PITCH_B + h * 2) = hiB;
                    *(unsigned*)(base + K_LO_B + (r + 8) * QK_PITCH_B + h * 2) = loB;
                } else {
                    // vt[h][s]: element (h, r)=v0, (h+1, r)=v1, (h, r+8)=v2, (h+1, r+8)=v3
                    *(unsigned short*)(base + VT_HI_B + h * VT_PITCH_B + r * 2)           = (unsigned short)(hiA & 0xFFFF);
                    *(unsigned short*)(base + VT_HI_B + (h + 1) * VT_PITCH_B + r * 2)     = (unsigned short)(hiA >> 16);
                    *(unsigned short*)(base + VT_LO_B + h * VT_PITCH_B + r * 2)           = (unsigned short)(loA & 0xFFFF);
                    *(unsigned short*)(base + VT_LO_B + (h + 1) * VT_PITCH_B + r * 2)     = (unsigned short)(loA >> 16);
                    *(unsigned short*)(base + VT_HI_B + h * VT_PITCH_B + (r + 8) * 2)     = (unsigned short)(hiB & 0xFFFF);
                    *(unsigned short*)(base + VT_HI_B + (h + 1) * VT_PITCH_B + (r + 8) * 2) = (unsigned short)(hiB >> 16);
                    *(unsigned short*)(base + VT_LO_B + h * VT_PITCH_B + (r + 8) * 2)     = (unsigned short)(loB & 0xFFFF);
                    *(unsigned short*)(base + VT_LO_B + (h + 1) * VT_PITCH_B + (r + 8) * 2) = (unsigned short)(loB >> 16);
                }
            }
        }
    }
    __syncthreads();

    // ---- Phase 2: S = Q @ K^T via MMA (causal tile list) ----
    {
        const int arow  = (lane & 15);
        const int acolB = (lane >> 4) * 16;            // byte offset of k-half
        const int brow  = (lane & 7);
        const int bcolB = ((lane >> 3) & 1) * 16;
        for (int i = warp; i < 72; i += 16) {
            int tb = TB72[i], st = ST72[i];
            float c[4] = {0.f, 0.f, 0.f, 0.f};
            unsigned aqb = smb + Q_HI_B + (unsigned)((tb * 16 + arow) * QK_PITCH_B) + acolB;
            unsigned akb = smb + K_HI_B + (unsigned)((st * 8 + brow) * QK_PITCH_B) + bcolB;
#pragma unroll
            for (int kg = 0; kg < 4; ++kg) {
                unsigned qh[4], ql[4], kh[2], kl[2];
                LDMX4(qh, aqb + kg * 32);
                LDMX4(ql, aqb + kg * 32 + (Q_LO_B - Q_HI_B));
                LDMX2(kh, akb + kg * 32);
                LDMX2(kl, akb + kg * 32 + (K_LO_B - K_HI_B));
                mma_bf16(c, qh, kh[0], kh[1]);
                mma_bf16(c, ql, kh[0], kh[1]);
                mma_bf16(c, qh, kl[0], kl[1]);
            }
            int trow = tb * 16 + (lane >> 2);
            int scol = st * 8 + (lane & 3) * 2;
            *(float2*)&S[trow * TT + scol]       = make_float2(c[0], c[1]);
            *(float2*)&S[(trow + 8) * TT + scol] = make_float2(c[2], c[3]);
        }
    }
    __syncthreads();

    // ---- Phase 3: causal softmax; emit P as bf16 hi/lo ----
    {
        char* phi = (char*)data + P_HI_B;
        char* plo = (char*)data + P_LO_B;
        for (int rr = 0; rr < 8; ++rr) {
            int t = warp * 8 + rr;
            float vals[4];
            float mx = -INFINITY;
#pragma unroll
            for (int j = 0; j < 4; ++j) {
                int s = lane + j * 32;
                vals[j] = (s <= t) ? S[t * TT + s] : -INFINITY;
                mx = fmaxf(mx, vals[j]);
            }
#pragma unroll
            for (int o = 16; o > 0; o >>= 1)
                mx = fmaxf(mx, __shfl_xor_sync(0xffffffffu, mx, o));
            float sum = 0.f;
#pragma unroll
            for (int j = 0; j < 4; ++j) {
                int s = lane + j * 32;
                vals[j] = (s <= t) ? __expf(vals[j] - mx) : 0.f;
                sum += vals[j];
            }
#pragma unroll
            for (int o = 16; o > 0; o >>= 1)
                sum += __shfl_xor_sync(0xffffffffu, sum, o);
            float inv = 1.f / sum;
#pragma unroll
            for (int j = 0; j < 4; ++j) {
                int s = lane + j * 32;
                float v = vals[j] * inv;                     // s>t -> exactly 0
                __nv_bfloat16 hv = __float2bfloat16_rn(v);
                __nv_bfloat16 lv = __float2bfloat16_rn(v - __bfloat162float(hv));
                *(unsigned short*)(phi + t * P_PITCH_B + s * 2) = __bfloat16_as_ushort(hv);
                *(unsigned short*)(plo + t * P_PITCH_B + s * 2) = __bfloat16_as_ushort(lv);
            }
        }
    }
    __syncthreads();

    // ---- Phase 4: out = P @ V via MMA (causal k-depth) ----
    {
        float* ob = out + (size_t)b * TT * HH;
        const int arow  = (lane & 15);
        const int acolB = (lane >> 4) * 16;
        const int brow  = (lane & 7);
        const int bcolB = ((lane >> 3) & 1) * 16;
        for (int i = warp; i < 64; i += 16) {
            int tb = i >> 3, nt = i & 7;
            float c[4] = {0.f, 0.f, 0.f, 0.f};
            unsigned apb = smb + P_HI_B  + (unsigned)((tb * 16 + arow) * P_PITCH_B)  + acolB;
            unsigned avb = smb + VT_HI_B + (unsigned)((nt * 8 + brow) * VT_PITCH_B) + bcolB;
            for (int kg = 0; kg <= tb; ++kg) {
                unsigned ph[4], pl[4], vh[2], vl[2];
                LDMX4(ph, apb + kg * 32);
                LDMX4(pl, apb + kg * 32 + (P_LO_B - P_HI_B));
                LDMX2(vh, avb + kg * 32);
                LDMX2(vl, avb + kg * 32 + (VT_LO_B - VT_HI_B));
                mma_bf16(c, ph, vh[0], vh[1]);
                mma_bf16(c, pl, vh[0], vh[1]);
                mma_bf16(c, ph, vl[0], vl[1]);
            }
            int trow = tb * 16 + (lane >> 2);
            int hcol = nt * 8 + (lane & 3) * 2;
            *(float2*)&ob[trow * HH + hcol]       = make_float2(c[0], c[1]);
            *(float2*)&ob[(trow + 8) * HH + hcol] = make_float2(c[2], c[3]);
        }
    }
}

extern "C" void kernel_launch(void* const* d_in, const int* in_sizes, int n_in,
                              void* d_out, int out_size)
{
    const float* x  = (const float*)d_in[0];
    const float* Wk = (const float*)d_in[1];
    const float* Wq = (const float*)d_in[2];
    const float* Wv = (const float*)d_in[3];
    float* out = (float*)d_out;

    static int smem_set = 0;
    if (!smem_set) {
        cudaFuncSetAttribute(head_attn_mma,
                             cudaFuncAttributeMaxDynamicSharedMemorySize,
                             SMEM_BYTES);
        smem_set = 1;
    }
    prep_w<<<(NK16 * NTILES * 32 + 255) / 256, 256>>>(Wk, Wq, Wv);
    head_attn_mma<<<BB, 512, SMEM_BYTES>>>(x, out);
}

// round 13
// speedup vs baseline: 4.3077x; 1.1468x over previous
#include <cuda_runtime.h>
#include <cuda_bf16.h>
#include <math.h>
#include <stdint.h>

// ---------------- problem constants ----------------
#define BB   1024
#define TT   128
#define CC   1024
#define HH   64
#define N3   192
#define KCH  32
#define NCHUNKS (CC/KCH)    // 32
#define NK16 (CC/16)        // 64
#define NTILES (N3/8)       // 24

// ---------------- smem layout (byte offsets) ----------------
// phase 1: x staging 2x(hi[128][20]u32|lo[128][20]u32) @0 (40960 B)
//          B staging 3 x 24576 B @40960 (ends 114688)
// post-projection (all dead during phase 1):
//   q_hi/q_lo/k_hi/k_lo [128][72]bf16 (pitch 144B), vt_hi/lo [64][136]bf16,
//   S [128][128] fp32, p_hi/p_lo [128][136]bf16 (overlap q/k)
#define XS_PITCH   20
#define XS_BUF_U32 (2*TT*XS_PITCH)
#define STAGE_B    20480
#define BST_B      40960
#define BCHUNK_B   24576            // 2 k16 * 24 nt * 32 lanes * 16B
#define Q_HI_B   0
#define Q_LO_B   18432
#define K_HI_B   36864
#define K_LO_B   55296
#define VT_HI_B  73728
#define VT_LO_B  91136
#define S_B      108544
#define P_HI_B   0
#define P_LO_B   34816
#define SMEM_BYTES 174080
#define QK_PITCH_B 144
#define VT_PITCH_B 272
#define P_PITCH_B  272

// B pre-packed in m16n8k16 bf16 fragment order, hi+lo fused
__device__ __align__(16) uint4 Bfrag_g[NK16 * NTILES * 32];

__device__ const unsigned char TB72[72] = {
    0,0, 1,1,1,1, 2,2,2,2,2,2, 3,3,3,3,3,3,3,3,
    4,4,4,4,4,4,4,4,4,4, 5,5,5,5,5,5,5,5,5,5,5,5,
    6,6,6,6,6,6,6,6,6,6,6,6,6,6, 7,7,7,7,7,7,7,7,7,7,7,7,7,7,7,7};
__device__ const unsigned char ST72[72] = {
    0,1, 0,1,2,3, 0,1,2,3,4,5, 0,1,2,3,4,5,6,7,
    0,1,2,3,4,5,6,7,8,9, 0,1,2,3,4,5,6,7,8,9,10,11,
    0,1,2,3,4,5,6,7,8,9,10,11,12,13, 0,1,2,3,4,5,6,7,8,9,10,11,12,13,14,15};

// ---------------- helpers ----------------
__device__ __forceinline__ uint32_t smem_u32(const void* p) {
    uint32_t a;
    asm("{ .reg .u64 t; cvta.to.shared.u64 t, %1; cvt.u32.u64 %0, t; }" : "=r"(a) : "l"(p));
    return a;
}
__device__ __forceinline__ void split2(float a, float b, unsigned& hi, unsigned& lo) {
    __nv_bfloat16 ha = __float2bfloat16_rn(a);
    __nv_bfloat16 hb = __float2bfloat16_rn(b);
    float ra = a - __bfloat162float(ha);
    float rb = b - __bfloat162float(hb);
    __nv_bfloat16 la = __float2bfloat16_rn(ra);
    __nv_bfloat16 lb = __float2bfloat16_rn(rb);
    hi = ((unsigned)__bfloat16_as_ushort(hb) << 16) | __bfloat16_as_ushort(ha);
    lo = ((unsigned)__bfloat16_as_ushort(lb) << 16) | __bfloat16_as_ushort(la);
}
__device__ __forceinline__ void mma_bf16(float* d, const unsigned* a,
                                         unsigned b0, unsigned b1) {
    asm volatile(
        "mma.sync.aligned.m16n8k16.row.col.f32.bf16.bf16.f32 "
        "{%0,%1,%2,%3}, {%4,%5,%6,%7}, {%8,%9}, {%0,%1,%2,%3};"
        : "+f"(d[0]), "+f"(d[1]), "+f"(d[2]), "+f"(d[3])
        : "r"(a[0]), "r"(a[1]), "r"(a[2]), "r"(a[3]), "r"(b0), "r"(b1));
}
#define LDMX4(r, addr) asm volatile( \
    "ldmatrix.sync.aligned.m8n8.x4.shared.b16 {%0,%1,%2,%3}, [%4];" \
    : "=r"((r)[0]), "=r"((r)[1]), "=r"((r)[2]), "=r"((r)[3]) : "r"(addr))
#define LDMX2(r, addr) asm volatile( \
    "ldmatrix.sync.aligned.m8n8.x2.shared.b16 {%0,%1}, [%2];" \
    : "=r"((r)[0]), "=r"((r)[1]) : "r"(addr))
#define CP_ASYNC16(smem_addr, gptr) asm volatile( \
    "cp.async.cg.shared.global [%0], [%1], 16;" :: "r"(smem_addr), "l"(gptr))
#define CP_COMMIT() asm volatile("cp.async.commit_group;" ::: "memory")
#define CP_WAIT1()  asm volatile("cp.async.wait_group 1;" ::: "memory")

// ---------------- prep kernel ----------------
__global__ void prep_w(const float* __restrict__ Wk,
                       const float* __restrict__ Wq,
                       const float* __restrict__ Wv)
{
    int i = blockIdx.x * blockDim.x + threadIdx.x;
    if (i >= NK16 * NTILES * 32) return;
    int lane = i & 31;
    int rest = i >> 5;
    int nt   = rest % NTILES;
    int k16  = rest / NTILES;
    int n    = nt * 8 + (lane >> 2);
    int mat  = n >> 6;
    int h    = n & 63;
    const float* W = (mat == 0) ? Wq : (mat == 1) ? Wk : Wv;
    int kb = k16 * 16 + 2 * (lane & 3);
    float w00 = W[kb * HH + h];
    float w01 = W[(kb + 1) * HH + h];
    float w10 = W[(kb + 8) * HH + h];
    float w11 = W[(kb + 9) * HH + h];
    uint4 v;
    split2(w00, w01, v.x, v.z);
    split2(w10, w11, v.y, v.w);
    Bfrag_g[i] = v;
}

// ---------------- main fused kernel ----------------
__global__ __launch_bounds__(512, 1)
void head_attn_mma(const float* __restrict__ x, float* __restrict__ out)
{
    extern __shared__ float data[];
    const uint32_t smb = smem_u32(data);
    float* S = (float*)((char*)data + S_B);
    unsigned* xsb = (unsigned*)data;

    const int b     = blockIdx.x;
    const int tid   = threadIdx.x;
    const int warp  = tid >> 5;
    const int lane  = tid & 31;
    const int warpM = warp >> 2;
    const int warpN = warp & 3;
    const float* xb = x + (size_t)b * TT * CC;

    // ---- Phase 1: QKV projection (bf16 m16n8k16, 3-term split) ----
    float acc[2][6][4];
#pragma unroll
    for (int bk = 0; bk < 2; ++bk)
#pragma unroll
        for (int nt = 0; nt < 6; ++nt)
#pragma unroll
            for (int j = 0; j < 4; ++j) acc[bk][nt][j] = 0.f;

    const int prow0 = tid >> 3,          pj40 = tid & 7;
    const int prow1 = (tid + 512) >> 3,  pj41 = (tid + 512) & 7;
    float4 pf0 = ((const float4*)(xb + (size_t)prow0 * CC))[pj40];
    float4 pf1 = ((const float4*)(xb + (size_t)prow1 * CC))[pj41];

    // ---- prologue: cp.async B(0), B(1); stage x(0); prefetch x(1) ----
    {
        const uint4* g0 = Bfrag_g;                       // chunk 0 span
        const uint4* g1 = Bfrag_g + 2 * NTILES * 32;     // chunk 1 span
        unsigned s0 = smb + BST_B;                       // buf 0
        unsigned s1 = smb + BST_B + BCHUNK_B;            // buf 1
#pragma unroll
        for (int t = 0; t < 3; ++t) {
            int i = tid + t * 512;
            CP_ASYNC16(s0 + i * 16, g0 + i);
        }
        CP_COMMIT();
#pragma unroll
        for (int t = 0; t < 3; ++t) {
            int i = tid + t * 512;
            CP_ASYNC16(s1 + i * 16, g1 + i);
        }
        CP_COMMIT();
    }
    {
        unsigned* hi0 = xsb;
        unsigned* lo0 = xsb + TT * XS_PITCH;
        unsigned h, l;
        split2(pf0.x, pf0.y, h, l);
        hi0[prow0 * XS_PITCH + pj40 * 2]     = h; lo0[prow0 * XS_PITCH + pj40 * 2]     = l;
        split2(pf0.z, pf0.w, h, l);
        hi0[prow0 * XS_PITCH + pj40 * 2 + 1] = h; lo0[prow0 * XS_PITCH + pj40 * 2 + 1] = l;
        split2(pf1.x, pf1.y, h, l);
        hi0[prow1 * XS_PITCH + pj41 * 2]     = h; lo0[prow1 * XS_PITCH + pj41 * 2]     = l;
        split2(pf1.z, pf1.w, h, l);
        hi0[prow1 * XS_PITCH + pj41 * 2 + 1] = h; lo0[prow1 * XS_PITCH + pj41 * 2 + 1] = l;
    }
    pf0 = ((const float4*)(xb + (size_t)prow0 * CC + KCH))[pj40];
    pf1 = ((const float4*)(xb + (size_t)prow1 * CC + KCH))[pj41];
    CP_WAIT1();          // B(0) landed (B(1) may fly)
    __syncthreads();

    const unsigned a_off = (unsigned)((warpM * 32 + (lane & 15)) * 80 + (lane >> 4) * 16);

    int bbuf = 0;   // ch % 3
    for (int ch = 0; ch < NCHUNKS; ++ch) {
        // issue cp.async for B(ch+2) into buf (ch+2)%3  (last read at ch-1, barrier-separated)
        if (ch + 2 < NCHUNKS) {
            int nb = bbuf + 2; if (nb >= 3) nb -= 3;
            const uint4* gsrc = Bfrag_g + (size_t)(ch + 2) * 2 * NTILES * 32;
            unsigned sdst = smb + BST_B + (unsigned)(nb * BCHUNK_B);
#pragma unroll
            for (int t = 0; t < 3; ++t) {
                int i = tid + t * 512;
                CP_ASYNC16(sdst + i * 16, gsrc + i);
            }
        }
        CP_COMMIT();   // always commit (empty group near the tail keeps wait counts sane)

        // stage x(ch+1)
        if (ch + 1 < NCHUNKS) {
            unsigned* hin = xsb + ((ch + 1) & 1) * XS_BUF_U32;
            unsigned* lon = hin + TT * XS_PITCH;
            unsigned h, l;
            split2(pf0.x, pf0.y, h, l);
            hin[prow0 * XS_PITCH + pj40 * 2]     = h; lon[prow0 * XS_PITCH + pj40 * 2]     = l;
            split2(pf0.z, pf0.w, h, l);
            hin[prow0 * XS_PITCH + pj40 * 2 + 1] = h; lon[prow0 * XS_PITCH + pj40 * 2 + 1] = l;
            split2(pf1.x, pf1.y, h, l);
            hin[prow1 * XS_PITCH + pj41 * 2]     = h; lon[prow1 * XS_PITCH + pj41 * 2]     = l;
            split2(pf1.z, pf1.w, h, l);
            hin[prow1 * XS_PITCH + pj41 * 2 + 1] = h; lon[prow1 * XS_PITCH + pj41 * 2 + 1] = l;
        }
        if (ch + 2 < NCHUNKS) {
            int c0n = (ch + 2) * KCH;
            pf0 = ((const float4*)(xb + (size_t)prow0 * CC + c0n))[pj40];
            pf1 = ((const float4*)(xb + (size_t)prow1 * CC + c0n))[pj41];
        }

        // compute chunk ch: x from smem buf ch&1, B from smem buf ch%3
        const unsigned hib = smb + (unsigned)((ch & 1) * STAGE_B);
        const unsigned lob = hib + TT * XS_PITCH * 4;
        const uint4* bbase = (const uint4*)((char*)data + BST_B + bbuf * BCHUNK_B);
#pragma unroll
        for (int g = 0; g < 2; ++g) {
            unsigned ah0[4], al0[4], ah1[4], al1[4];
            unsigned ad  = hib + a_off + g * 32;
            unsigned al_ = lob + a_off + g * 32;
            LDMX4(ah0, ad);
            LDMX4(al0, al_);
            LDMX4(ah1, ad + 16 * 80);
            LDMX4(al1, al_ + 16 * 80);

            const uint4* bp = bbase + (g * NTILES + warpN * 6) * 32 + lane;
#pragma unroll
            for (int nt = 0; nt < 6; ++nt) {
                uint4 b4 = bp[nt * 32];
                mma_bf16(acc[0][nt], ah0, b4.x, b4.y);
                mma_bf16(acc[0][nt], al0, b4.x, b4.y);
                mma_bf16(acc[0][nt], ah0, b4.z, b4.w);
                mma_bf16(acc[1][nt], ah1, b4.x, b4.y);
                mma_bf16(acc[1][nt], al1, b4.x, b4.y);
                mma_bf16(acc[1][nt], ah1, b4.z, b4.w);
            }
        }

        CP_WAIT1();        // B(ch+1) landed; B(ch+2) may still fly
        __syncthreads();   // x(ch+1) + B(ch+1) visible CTA-wide; buffers rotate
        if (++bbuf == 3) bbuf = 0;
    }

    // ---- scatter: Q/K -> bf16 hi/lo rows; V -> vt[h][s] bf16 hi/lo ----
    {
        char* base = (char*)data;
#pragma unroll
        for (int bk = 0; bk < 2; ++bk) {
#pragma unroll
            for (int nt = 0; nt < 6; ++nt) {
                int r   = warpM * 32 + bk * 16 + (lane >> 2);
                int n   = warpN * 48 + nt * 8 + (lane & 3) * 2;
                int mat = n >> 6;
                int h   = n & 63;
                unsigned hiA, loA, hiB, loB;
                split2(acc[bk][nt][0], acc[bk][nt][1], hiA, loA);
                split2(acc[bk][nt][2], acc[bk][nt][3], hiB, loB);
                if (mat == 0) {
                    *(unsigned*)(base + Q_HI_B + r * QK_PITCH_B + h * 2)       = hiA;
                    *(unsigned*)(base + Q_LO_B + r * QK_PITCH_B + h * 2)       = loA;
                    *(unsigned*)(base + Q_HI_B + (r + 8) * QK_PITCH_B + h * 2) = hiB;
                    *(unsigned*)(base + Q_LO_B + (r + 8) * QK_PITCH_B + h * 2) = loB;
                } else if (mat == 1) {
                    *(unsigned*)(base + K_HI_B + r * QK_PITCH_B + h * 2)       = hiA;
                    *(unsigned*)(base + K_LO_B + r * QK_PITCH_B + h * 2)       = loA;
                    *(unsigned*)(base + K_HI_B + (r + 8) * QK_PITCH_B + h * 2) = hiB;
                    *(unsigned*)(base + K_LO_B + (r + 8) * QK_PITCH_B + h * 2) = loB;
                } else {
                    *(unsigned short*)(base + VT_HI_B + h * VT_PITCH_B + r * 2)             = (unsigned short)(hiA & 0xFFFF);
                    *(unsigned short*)(base + VT_HI_B + (h + 1) * VT_PITCH_B + r * 2)       = (unsigned short)(hiA >> 16);
                    *(unsigned short*)(base + VT_LO_B + h * VT_PITCH_B + r * 2)             = (unsigned short)(loA & 0xFFFF);
                    *(unsigned short*)(base + VT_LO_B + (h + 1) * VT_PITCH_B + r * 2)       = (unsigned short)(loA >> 16);
                    *(unsigned short*)(base + VT_HI_B + h * VT_PITCH_B + (r + 8) * 2)       = (unsigned short)(hiB & 0xFFFF);
                    *(unsigned short*)(base + VT_HI_B + (h + 1) * VT_PITCH_B + (r + 8) * 2) = (unsigned short)(hiB >> 16);
                    *(unsigned short*)(base + VT_LO_B + h * VT_PITCH_B + (r + 8) * 2)       = (unsigned short)(loB & 0xFFFF);
                    *(unsigned short*)(base + VT_LO_B + (h + 1) * VT_PITCH_B + (r + 8) * 2) = (unsigned short)(loB >> 16);
                }
            }
        }
    }
    __syncthreads();

    // ---- Phase 2: S = Q @ K^T via MMA (causal tile list) ----
    {
        const int arow  = (lane & 15);
        const int acolB = (lane >> 4) * 16;
        const int brow  = (lane & 7);
        const int bcolB = ((lane >> 3) & 1) * 16;
        for (int i = warp; i < 72; i += 16) {
            int tb = TB72[i], st = ST72[i];
            float c[4] = {0.f, 0.f, 0.f, 0.f};
            unsigned aqb = smb + Q_HI_B + (unsigned)((tb * 16 + arow) * QK_PITCH_B) + acolB;
            unsigned akb = smb + K_HI_B + (unsigned)((st * 8 + brow) * QK_PITCH_B) + bcolB;
#pragma unroll
            for (int kg = 0; kg < 4; ++kg) {
                unsigned qh[4], ql[4], kh[2], kl[2];
                LDMX4(qh, aqb + kg * 32);
                LDMX4(ql, aqb + kg * 32 + (Q_LO_B - Q_HI_B));
                LDMX2(kh, akb + kg * 32);
                LDMX2(kl, akb + kg * 32 + (K_LO_B - K_HI_B));
                mma_bf16(c, qh, kh[0], kh[1]);
                mma_bf16(c, ql, kh[0], kh[1]);
                mma_bf16(c, qh, kl[0], kl[1]);
            }
            int trow = tb * 16 + (lane >> 2);
            int scol = st * 8 + (lane & 3) * 2;
            *(float2*)&S[trow * TT + scol]       = make_float2(c[0], c[1]);
            *(float2*)&S[(trow + 8) * TT + scol] = make_float2(c[2], c[3]);
        }
    }
    __syncthreads();

    // ---- Phase 3: causal softmax; emit P as bf16 hi/lo ----
    {
        char* phi = (char*)data + P_HI_B;
        char* plo = (char*)data + P_LO_B;
        for (int rr = 0; rr < 8; ++rr) {
            int t = warp * 8 + rr;
            float vals[4];
            float mx = -INFINITY;
#pragma unroll
            for (int j = 0; j < 4; ++j) {
                int s = lane + j * 32;
                vals[j] = (s <= t) ? S[t * TT + s] : -INFINITY;
                mx = fmaxf(mx, vals[j]);
            }
#pragma unroll
            for (int o = 16; o > 0; o >>= 1)
                mx = fmaxf(mx, __shfl_xor_sync(0xffffffffu, mx, o));
            float sum = 0.f;
#pragma unroll
            for (int j = 0; j < 4; ++j) {
                int s = lane + j * 32;
                vals[j] = (s <= t) ? __expf(vals[j] - mx) : 0.f;
                sum += vals[j];
            }
#pragma unroll
            for (int o = 16; o > 0; o >>= 1)
                sum += __shfl_xor_sync(0xffffffffu, sum, o);
            float inv = 1.f / sum;
#pragma unroll
            for (int j = 0; j < 4; ++j) {
                int s = lane + j * 32;
                float v = vals[j] * inv;
                __nv_bfloat16 hv = __float2bfloat16_rn(v);
                __nv_bfloat16 lv = __float2bfloat16_rn(v - __bfloat162float(hv));
                *(unsigned short*)(phi + t * P_PITCH_B + s * 2) = __bfloat16_as_ushort(hv);
                *(unsigned short*)(plo + t * P_PITCH_B + s * 2) = __bfloat16_as_ushort(lv);
            }
        }
    }
    __syncthreads();

    // ---- Phase 4: out = P @ V via MMA (causal k-depth) ----
    {
        float* ob = out + (size_t)b * TT * HH;
        const int arow  = (lane & 15);
        const int acolB = (lane >> 4) * 16;
        const int brow  = (lane & 7);
        const int bcolB = ((lane >> 3) & 1) * 16;
        for (int i = warp; i < 64; i += 16) {
            int tb = i >> 3, nt = i & 7;
            float c[4] = {0.f, 0.f, 0.f, 0.f};
            unsigned apb = smb + P_HI_B  + (unsigned)((tb * 16 + arow) * P_PITCH_B)  + acolB;
            unsigned avb = smb + VT_HI_B + (unsigned)((nt * 8 + brow) * VT_PITCH_B) + bcolB;
            for (int kg = 0; kg <= tb; ++kg) {
                unsigned ph[4], pl[4], vh[2], vl[2];
                LDMX4(ph, apb + kg * 32);
                LDMX4(pl, apb + kg * 32 + (P_LO_B - P_HI_B));
                LDMX2(vh, avb + kg * 32);
                LDMX2(vl, avb + kg * 32 + (VT_LO_B - VT_HI_B));
                mma_bf16(c, ph, vh[0], vh[1]);
                mma_bf16(c, pl, vh[0], vh[1]);
                mma_bf16(c, ph, vl[0], vl[1]);
            }
            int trow = tb * 16 + (lane >> 2);
            int hcol = nt * 8 + (lane & 3) * 2;
            *(float2*)&ob[trow * HH + hcol]       = make_float2(c[0], c[1]);
            *(float2*)&ob[(trow + 8) * HH + hcol] = make_float2(c[2], c[3]);
        }
    }
}

extern "C" void kernel_launch(void* const* d_in, const int* in_sizes, int n_in,
                              void* d_out, int out_size)
{
    const float* x  = (const float*)d_in[0];
    const float* Wk = (const float*)d_in[1];
    const float* Wq = (const float*)d_in[2];
    const float* Wv = (const float*)d_in[3];
    float* out = (float*)d_out;

    static int smem_set = 0;
    if (!smem_set) {
        cudaFuncSetAttribute(head_attn_mma,
                             cudaFuncAttributeMaxDynamicSharedMemorySize,
                             SMEM_BYTES);
        smem_set = 1;
    }
    prep_w<<<(NK16 * NTILES * 32 + 255) / 256, 256>>>(Wk, Wq, Wv);
    head_attn_mma<<<BB, 512, SMEM_BYTES>>>(x, out);
}